// round 5
// baseline (speedup 1.0000x reference)
#include <cuda_runtime.h>
#include <cuda_fp16.h>
#include <math.h>

#define T_STEPS 4096
#define VOCAB   1024
#define STATE   2048
#define CDIM    3072
#define NEL     (CDIM*CDIM)
#define NBLK    148
#define NTHR    768
#define NWARPS  24
#define PIN_L2  12
#define MAXPIN  33
#define PIN_BYTES (MAXPIN*CDIM*2)
#define SMEM_TOTAL (PIN_BYTES + 2*128*4)

#define CNT_CHUNK ((NWARPS-3)*32 + 32)   // 704: warps 3..23 sync + poller arrive
#define CNT_PUB   (NWARPS*32)            // 768: warps 0..22 arrive + warp23 sync

#define BAR_SYNC(id,cnt)   asm volatile("bar.sync %0, %1;"   :: "r"(id), "r"(cnt) : "memory")
#define BAR_ARRIVE(id,cnt) asm volatile("bar.arrive %0, %1;" :: "r"(id), "r"(cnt) : "memory")

// ---- persistent device state ----
__device__ __half   g_wh[3*(size_t)NEL];
__device__ float    g_h1[2][CDIM];
__device__ float    g_h2[2][CDIM];
__device__ float    g_state[2][STATE];
__device__ unsigned g_cnt[3][3];          // cumulative per (producer-layer, chunk)
__device__ unsigned g_scount, g_sflag;

// ---- launch-start barrier: last arriver resets counters, then releases ----
__device__ __forceinline__ void start_barrier() {
    __syncthreads();
    if (threadIdx.x == 0) {
        unsigned F0;
        asm volatile("ld.volatile.global.u32 %0,[%1];" : "=r"(F0) : "l"(&g_sflag) : "memory");
        unsigned a = atomicAdd(&g_scount, 1u) + 1u;
        if (a == (unsigned)gridDim.x) {
            for (int l = 0; l < 3; l++)
                for (int k = 0; k < 3; k++) g_cnt[l][k] = 0u;
            atomicExch(&g_scount, 0u);
            __threadfence();
            atomicAdd(&g_sflag, 1u);
        } else {
            unsigned f;
            do {
                asm volatile("ld.volatile.global.u32 %0,[%1];" : "=r"(f) : "l"(&g_sflag) : "memory");
            } while (f == F0);
            __threadfence();
        }
    }
    __syncthreads();
}

// ---- fp32->fp16 conversion (once per launch) ----
__global__ void conv_kernel(const float* __restrict__ W1,
                            const float* __restrict__ W2,
                            const float* __restrict__ W3) {
    size_t i = (size_t)blockIdx.x * blockDim.x + threadIdx.x;
    size_t stride = (size_t)gridDim.x * blockDim.x;
    const float2* w1 = (const float2*)W1;
    const float2* w2 = (const float2*)W2;
    const float2* w3 = (const float2*)W3;
    __half2* o1 = (__half2*)g_wh;
    __half2* o2 = (__half2*)(g_wh + (size_t)NEL);
    __half2* o3 = (__half2*)(g_wh + 2*(size_t)NEL);
    for (; i < NEL/2; i += stride) {
        float2 a = w1[i]; o1[i] = __floats2half2_rn(a.x, a.y);
        float2 b = w2[i]; o2[i] = __floats2half2_rn(b.x, b.y);
        float2 c = w3[i]; o3[i] = __floats2half2_rn(c.x, c.y);
    }
}

// ---- consumer gate: spin until producer counter reaches target ----
__device__ __forceinline__ void gate_poll(int l, int c, int t, const int* Tk) {
    const unsigned* cp = 0; unsigned tgt = 0;
    if (l == 0) {
        if (c > 0 && t > 0) { cp = &g_cnt[2][c]; tgt = (unsigned)t * (unsigned)Tk[c]; }
    } else {
        cp = &g_cnt[l-1][c]; tgt = (unsigned)(t+1) * (unsigned)Tk[c];
    }
    if (cp) {
        unsigned v;
        do {
            asm volatile("ld.volatile.global.u32 %0,[%1];" : "=r"(v) : "l"(cp) : "memory");
        } while (v < tgt);
        __threadfence();   // acquire
    }
}

// ---- weight loads: 4 rows x 2 sub-iterations (8 uint2 = 32 halfs) ----
template<bool PIN>
__device__ __forceinline__ void wload(uint2 wb[8],
    const __half* w0, const __half* w1, const __half* w2, const __half* w3,
    int kb, int lane)
{
    int k0 = kb + lane*4;
    int k1 = k0 + 128;
    if (PIN) {
        wb[0] = *(const uint2*)(w0+k0); wb[1] = *(const uint2*)(w1+k0);
        wb[2] = *(const uint2*)(w2+k0); wb[3] = *(const uint2*)(w3+k0);
        wb[4] = *(const uint2*)(w0+k1); wb[5] = *(const uint2*)(w1+k1);
        wb[6] = *(const uint2*)(w2+k1); wb[7] = *(const uint2*)(w3+k1);
    } else {
        wb[0] = __ldg((const uint2*)(w0+k0)); wb[1] = __ldg((const uint2*)(w1+k0));
        wb[2] = __ldg((const uint2*)(w2+k0)); wb[3] = __ldg((const uint2*)(w3+k0));
        wb[4] = __ldg((const uint2*)(w0+k1)); wb[5] = __ldg((const uint2*)(w1+k1));
        wb[6] = __ldg((const uint2*)(w2+k1)); wb[7] = __ldg((const uint2*)(w3+k1));
    }
}

__device__ __forceinline__ void fma8(const uint2 wb[8], float4 v0, float4 v1,
                                     float& a0, float& a1, float& a2, float& a3)
{
#define D(AC, W, V) do {                                                   \
    float2 fa = __half22float2(*(const __half2*)&(W).x);                   \
    float2 fb = __half22float2(*(const __half2*)&(W).y);                   \
    AC = fmaf(fa.x, (V).x, AC); AC = fmaf(fa.y, (V).y, AC);                \
    AC = fmaf(fb.x, (V).z, AC); AC = fmaf(fb.y, (V).w, AC); } while (0)
    D(a0, wb[0], v0); D(a1, wb[1], v0); D(a2, wb[2], v0); D(a3, wb[3], v0);
    D(a0, wb[4], v1); D(a1, wb[5], v1); D(a2, wb[6], v1); D(a3, wb[7], v1);
#undef D
}

// ---- one phase's accumulation for this warp (3 chunks, prefetched weights) ----
template<bool PIN>
__device__ __forceinline__ void phase_compute(
    const __half* w0, const __half* w1, const __half* w2, const __half* w3,
    const float* cb0, const float* cb1, const float* cb2,
    int l, int t, const int* Tk, int warp, int lane, int ks,
    float& a0, float& a1, float& a2, float& a3)
{
    uint2 wb[2][8];
    const int kb = ks*256;
    wload<PIN>(wb[0], w0, w1, w2, w3, kb, lane);     // chunk 0, before the gate
    const float* cbs[3] = {cb0, cb1, cb2};
#pragma unroll
    for (int c = 0; c < 3; c++) {
        if (warp < 3) {                               // poller warps: direct poll
            if (c != warp) {
                if (lane == 0) gate_poll(l, c, t, Tk);
                __syncwarp();
            }
        } else {
            BAR_SYNC(1 + c, CNT_CHUNK);
        }
        const float4* s4 = (const float4*)cbs[c];
        float4 v0 = __ldcg(s4 + ks*64 + lane);
        float4 v1 = __ldcg(s4 + ks*64 + 32 + lane);
        if (c < 2)
            wload<PIN>(wb[(c+1)&1], w0, w1, w2, w3, (c+1)*1024 + kb, lane);
        fma8(wb[c&1], v0, v1, a0, a1, a2, a3);
    }
}

__global__ void __launch_bounds__(NTHR, 1)
rnn_kernel(const float* __restrict__ x,  const float* __restrict__ state0,
           const float* __restrict__ B1, const float* __restrict__ B2,
           const float* __restrict__ B3, float* __restrict__ out) {
    extern __shared__ char smem[];
    __half* wpin = (__half*)smem;
    float*  spre = (float*)(smem + PIN_BYTES);   // [2][128]

    const int tid  = threadIdx.x;
    const int lane = tid & 31;
    const int warp = tid >> 5;
    const int b    = blockIdx.x;

    const int rcount = 20 + (b < 112 ? 1 : 0);
    const int rstart = b*20 + (b < 112 ? b : 112);
    const int klo = rstart >> 10;
    const int khi = (rstart + rcount - 1) >> 10;

    start_barrier();

    // ---- stage pinned rows: all of layer1 + first 12 rows of layer2 ----
    {
        const int npin = rcount + PIN_L2;
        int nvec = npin * (CDIM/8);
        for (int idx = tid; idx < nvec; idx += NTHR) {
            int p = idx / (CDIM/8);
            int c = idx % (CDIM/8);
            int l = (p < rcount) ? 0 : 1;
            int local = (p < rcount) ? p : p - rcount;
            const uint4* src = (const uint4*)(g_wh + (size_t)l*NEL + (size_t)(rstart+local)*CDIM);
            ((uint4*)(wpin + p*CDIM))[c] = src[c];
        }
    }
    __syncthreads();

    // producers per chunk
    int Tk[3];
#pragma unroll
    for (int k = 0; k < 3; k++) {
        int cnt = 0;
        for (int bb = 0; bb < NBLK; bb++) {
            int rs = 20*bb + (bb < 112 ? bb : 112);
            int rc = 20 + (bb < 112 ? 1 : 0);
            if (rs < (k+1)*1024 && rs + rc > k*1024) cnt++;
        }
        Tk[k] = cnt;
    }

    const int grp = warp >> 2;          // 0..5, 4 rows each
    const int ks  = warp & 3;
    const int r0  = grp * 4;
    const int l0 = min(r0,   rcount-1);
    const int l1 = min(r0+1, rcount-1);
    const int l2 = min(r0+2, rcount-1);
    const int l3 = min(r0+3, rcount-1);

    float myB1 = 0.f, myB2 = 0.f, myB3 = 0.f;
    if (warp == NWARPS-1 && lane < rcount) {
        myB1 = __ldg(&B1[rstart+lane]);
        myB2 = __ldg(&B2[rstart+lane]);
        myB3 = __ldg(&B3[rstart+lane]);
    }

    int par = 0;
    for (int t = 0; t < T_STEPS; t++) {
#pragma unroll
        for (int l = 0; l < 3; l++) {
            // poller warps: gate own chunk, then release the chunk barrier
            if (warp < 3) {
                if (lane == 0) gate_poll(l, warp, t, Tk);
                __syncwarp();
                BAR_ARRIVE(1 + warp, CNT_CHUNK);
            }

            // chunk base pointers
            const float *cb0, *cb1, *cb2;
            if (l == 0) {
                cb0 = x + (size_t)t * VOCAB;
                const float* sp = (t == 0) ? state0 : g_state[(t-1)&1];
                cb1 = sp; cb2 = sp + 1024;
            } else if (l == 1) {
                cb0 = g_h1[t&1]; cb1 = cb0 + 1024; cb2 = cb0 + 2048;
            } else {
                cb0 = g_h2[t&1]; cb1 = cb0 + 1024; cb2 = cb0 + 2048;
            }

            float a0 = 0.f, a1 = 0.f, a2 = 0.f, a3 = 0.f;
            bool pin = (l == 0) || (l == 1 && grp < 3);
            if (pin) {
                const __half* bb = (l == 0) ? wpin : wpin + rcount*CDIM;
                phase_compute<true >(bb + l0*CDIM, bb + l1*CDIM, bb + l2*CDIM, bb + l3*CDIM,
                                     cb0, cb1, cb2, l, t, Tk, warp, lane, ks, a0, a1, a2, a3);
            } else {
                const __half* bb = g_wh + (size_t)l*NEL;
                phase_compute<false>(bb + (size_t)(rstart+l0)*CDIM, bb + (size_t)(rstart+l1)*CDIM,
                                     bb + (size_t)(rstart+l2)*CDIM, bb + (size_t)(rstart+l3)*CDIM,
                                     cb0, cb1, cb2, l, t, Tk, warp, lane, ks, a0, a1, a2, a3);
            }

            // warp reduce + partial store
#pragma unroll
            for (int o = 16; o; o >>= 1) {
                a0 += __shfl_xor_sync(0xffffffffu, a0, o);
                a1 += __shfl_xor_sync(0xffffffffu, a1, o);
                a2 += __shfl_xor_sync(0xffffffffu, a2, o);
                a3 += __shfl_xor_sync(0xffffffffu, a3, o);
            }
            float* sp = spre + par*128 + ks*32;
            if (lane == 0) {
                if (r0   < rcount) sp[r0  ] = a0;
                if (r0+1 < rcount) sp[r0+1] = a1;
                if (r0+2 < rcount) sp[r0+2] = a2;
                if (r0+3 < rcount) sp[r0+3] = a3;
            }

            if (warp == NWARPS-1) {
                BAR_SYNC(4 + par, CNT_PUB);     // wait for all partials
                if (lane < rcount) {
                    int j = rstart + lane;
                    const float* q = spre + par*128;
                    float s = q[lane] + q[32+lane] + q[64+lane] + q[96+lane];
                    if (l == 0) {
                        __stcg(&g_h1[t&1][j], tanhf(s + myB1));
                    } else if (l == 1) {
                        __stcg(&g_h2[t&1][j], tanhf(s + myB2));
                    } else {
                        float o = s + myB3;
                        if (j < VOCAB) {
                            out[(size_t)t*VOCAB + j] = o;
                        } else {
                            __stcg(&g_state[t&1][j - VOCAB], o);
                            if (t == T_STEPS-1)
                                out[(size_t)T_STEPS*VOCAB + (j - VOCAB)] = o;
                        }
                    }
                }
                __syncwarp();
                if (lane == 0) {
                    __threadfence();            // release
                    atomicAdd(&g_cnt[l][klo], 1u);
                    if (khi != klo) atomicAdd(&g_cnt[l][khi], 1u);
                }
            } else {
                __threadfence_block();
                BAR_ARRIVE(4 + par, CNT_PUB);   // non-blocking: flow into next phase
            }
            par ^= 1;
        }
    }
}

extern "C" void kernel_launch(void* const* d_in, const int* in_sizes, int n_in,
                              void* d_out, int out_size) {
    const float* x  = (const float*)d_in[0];
    const float* st = (const float*)d_in[1];
    const float* W1 = (const float*)d_in[2];
    const float* B1 = (const float*)d_in[3];
    const float* W2 = (const float*)d_in[4];
    const float* B2 = (const float*)d_in[5];
    const float* W3 = (const float*)d_in[6];
    const float* B3 = (const float*)d_in[7];
    (void)in_sizes; (void)n_in; (void)out_size;

    cudaFuncSetAttribute(rnn_kernel, cudaFuncAttributeMaxDynamicSharedMemorySize, SMEM_TOTAL);

    conv_kernel<<<2048, 256>>>(W1, W2, W3);
    rnn_kernel<<<NBLK, NTHR, SMEM_TOTAL>>>(x, st, B1, B2, B3, (float*)d_out);
}

// round 7
// speedup vs baseline: 1.2396x; 1.2396x over previous
#include <cuda_runtime.h>
#include <cuda_fp16.h>
#include <math.h>

#define T_STEPS 4096
#define VOCAB   1024
#define STATE   2048
#define CDIM    3072
#define NEL     (CDIM*CDIM)
#define NBLK    148
#define NTHR    1024
#define NCOMPW  28
#define NCHUNK  3
#define CHUNK   1024
#define PIN_L2  12
#define MAXPIN  33
#define PIN_BYTES (MAXPIN*CDIM*2)
#define SV_OFF    PIN_BYTES
#define SPRE_OFF  (SV_OFF + CDIM*4)          // sv: 12288 B
#define SDONE_OFF (SPRE_OFF + 2*32*4*4)      // spre: 1024 B
#define SMEM_TOTAL (SDONE_OFF + (2*8+2)*4)   // sdone[2][8] + bdone[2]

#define CNT_FWD (NCOMPW*32 + 32)   // 928
#define BAR_SYNC(id,cnt)   asm volatile("bar.sync %0, %1;"   :: "r"(id), "r"(cnt) : "memory")
#define BAR_ARRIVE(id,cnt) asm volatile("bar.arrive %0, %1;" :: "r"(id), "r"(cnt) : "memory")

// ---- persistent device state ----
__device__ __half   g_wh[3*(size_t)NEL];
__device__ float    g_h1[2][CDIM];
__device__ float    g_h2[2][CDIM];
__device__ float    g_state[2][STATE];
__device__ unsigned g_cnt[3][NCHUNK];
__device__ unsigned g_scount, g_sflag;

__device__ __forceinline__ void start_barrier() {
    __syncthreads();
    if (threadIdx.x == 0) {
        unsigned F0;
        asm volatile("ld.volatile.global.u32 %0,[%1];" : "=r"(F0) : "l"(&g_sflag) : "memory");
        unsigned a = atomicAdd(&g_scount, 1u) + 1u;
        if (a == (unsigned)gridDim.x) {
            for (int l = 0; l < 3; l++)
                for (int k = 0; k < NCHUNK; k++) g_cnt[l][k] = 0u;
            atomicExch(&g_scount, 0u);
            __threadfence();
            atomicAdd(&g_sflag, 1u);
        } else {
            unsigned f;
            do {
                asm volatile("ld.volatile.global.u32 %0,[%1];" : "=r"(f) : "l"(&g_sflag) : "memory");
            } while (f == F0);
            __threadfence();
        }
    }
    __syncthreads();
}

__global__ void conv_kernel(const float* __restrict__ W1,
                            const float* __restrict__ W2,
                            const float* __restrict__ W3) {
    size_t i = (size_t)blockIdx.x * blockDim.x + threadIdx.x;
    size_t stride = (size_t)gridDim.x * blockDim.x;
    const float2* w1 = (const float2*)W1;
    const float2* w2 = (const float2*)W2;
    const float2* w3 = (const float2*)W3;
    __half2* o1 = (__half2*)g_wh;
    __half2* o2 = (__half2*)(g_wh + (size_t)NEL);
    __half2* o3 = (__half2*)(g_wh + 2*(size_t)NEL);
    for (; i < NEL/2; i += stride) {
        float2 a = w1[i]; o1[i] = __floats2half2_rn(a.x, a.y);
        float2 b = w2[i]; o2[i] = __floats2half2_rn(b.x, b.y);
        float2 c = w3[i]; o3[i] = __floats2half2_rn(c.x, c.y);
    }
}

// ---- accumulate 3 rows over the 3 chunks with per-chunk barriers (R3-proven) ----
template<bool PIN>
__device__ __forceinline__ void chunks_loop(
    const __half* w0, const __half* w1, const __half* w2,
    const float* __restrict__ sv, int ks, int lane,
    float& a0, float& a1, float& a2)
{
#pragma unroll
    for (int c = 0; c < NCHUNK; c++) {
        BAR_SYNC(1 + c, CNT_FWD);
        int kb = c*CHUNK + ks*256;
#pragma unroll
        for (int i = 0; i < 2; i++) {
            int k = kb + (i*32 + lane)*4;
            float4 v = *(const float4*)(sv + k);
#define ROW(AC, WP) do {                                                   \
            uint2 wa = PIN ? *(const uint2*)((WP) + k)                     \
                           : __ldg((const uint2*)((WP) + k));              \
            float2 fa = __half22float2(*(const __half2*)&wa.x);            \
            float2 fb = __half22float2(*(const __half2*)&wa.y);            \
            AC = fmaf(fa.x, v.x, AC); AC = fmaf(fa.y, v.y, AC);            \
            AC = fmaf(fb.x, v.z, AC); AC = fmaf(fb.y, v.w, AC); } while (0)
            ROW(a0, w0); ROW(a1, w1); ROW(a2, w2);
#undef ROW
        }
        BAR_ARRIVE(4 + c, CNT_FWD);
    }
}

__global__ void __launch_bounds__(NTHR, 1)
rnn_kernel(const float* __restrict__ x,  const float* __restrict__ state0,
           const float* __restrict__ B1, const float* __restrict__ B2,
           const float* __restrict__ B3, float* __restrict__ out) {
    extern __shared__ char smem[];
    __half* wpin = (__half*)smem;
    float*  sv   = (float*)(smem + SV_OFF);
    float*  spre = (float*)(smem + SPRE_OFF);                 // [2][32][4]
    unsigned* sdone = (unsigned*)(smem + SDONE_OFF);          // [2][8]
    unsigned* bdone = (unsigned*)(smem + SDONE_OFF + 2*8*4);  // [2]

    const int tid  = threadIdx.x;
    const int lane = tid & 31;
    const int warp = tid >> 5;
    const int b    = blockIdx.x;

    const int rcount = 20 + (b < 112 ? 1 : 0);
    const int rstart = b*20 + (b < 112 ? b : 112);
    const int klo = rstart >> 10;
    const int khi = (rstart + rcount - 1) >> 10;

    if (tid < 18) ((unsigned*)(smem + SDONE_OFF))[tid] = 0u;

    start_barrier();

    // ---- stage pinned weight rows (layer1 all + 12 rows of layer2) ----
    {
        const int npin = rcount + PIN_L2;
        int nvec = npin * (CDIM/8);
        for (int idx = tid; idx < nvec; idx += NTHR) {
            int p = idx / (CDIM/8);
            int c = idx % (CDIM/8);
            int l = (p < rcount) ? 0 : 1;
            int local = (p < rcount) ? p : p - rcount;
            const uint4* src = (const uint4*)(g_wh + (size_t)l*NEL + (size_t)(rstart+local)*CDIM);
            ((uint4*)(wpin + p*CDIM))[c] = src[c];
        }
    }
    __syncthreads();

    if (warp == 31) return;   // idle warp

    int Tk[NCHUNK];
#pragma unroll
    for (int k = 0; k < NCHUNK; k++) {
        int cnt = 0;
        for (int bb = 0; bb < NBLK; bb++) {
            int rs = 20*bb + (bb < 112 ? bb : 112);
            int rc = 20 + (bb < 112 ? 1 : 0);
            if (rs < (k+1)*CHUNK && rs + rc > k*CHUNK) cnt++;
        }
        Tk[k] = cnt;
    }

    if (warp >= NCOMPW) {
        // ================= STAGER WARP (one chunk each) =================
        const int c = warp - NCOMPW;
        const unsigned Tc = (unsigned)Tk[c];
        for (int t = 0; t < T_STEPS; t++) {
            for (int l = 0; l < 3; l++) {
                BAR_SYNC(4 + c, CNT_FWD);       // back-pressure (primed)
                const float* src;
                bool gated = true; unsigned tgt = 0; const unsigned* cp = 0;
                if (l == 0) {
                    if (c == 0) { src = x + (size_t)t*VOCAB; gated = false; }
                    else {
                        cp = &g_cnt[2][c]; tgt = (unsigned)t * Tc;
                        src = (t == 0) ? state0 + (c*CHUNK - VOCAB)
                                       : g_state[(t-1)&1] + (c*CHUNK - VOCAB);
                        gated = (t > 0);
                    }
                } else if (l == 1) {
                    cp = &g_cnt[0][c]; tgt = (unsigned)(t+1) * Tc;
                    src = g_h1[t&1] + c*CHUNK;
                } else {
                    cp = &g_cnt[1][c]; tgt = (unsigned)(t+1) * Tc;
                    src = g_h2[t&1] + c*CHUNK;
                }
                if (gated && lane == 0) {
                    unsigned v;
                    do {
                        asm volatile("ld.volatile.global.u32 %0,[%1];" : "=r"(v) : "l"(cp) : "memory");
                    } while (v < tgt);
                    __threadfence();
                }
                __syncwarp();
                const float4* s4 = (const float4*)src;
                float4* d4 = (float4*)(sv + c*CHUNK);
#pragma unroll
                for (int i = 0; i < CHUNK/128; i++)
                    d4[lane + 32*i] = __ldcg(&s4[lane + 32*i]);
                __threadfence_block();
                BAR_ARRIVE(1 + c, CNT_FWD);
            }
        }
    } else {
        // ================= COMPUTE WARP =================
        const int grp = warp >> 2;              // 0..6 (3 rows each)
        const int ks  = warp & 3;
        const int r0  = grp*3;
        const int l0 = min(r0,   rcount-1);
        const int l1 = min(r0+1, rcount-1);
        const int l2 = min(r0+2, rcount-1);

        // biases for the 3 rows this group publishes (ks==0, lanes 0..2)
        float pb1 = 0.f, pb2 = 0.f, pb3 = 0.f;
        if (ks == 0 && lane < 3 && (r0 + lane) < rcount) {
            int j = rstart + r0 + lane;
            pb1 = __ldg(&B1[j]); pb2 = __ldg(&B2[j]); pb3 = __ldg(&B3[j]);
        }

        // prime back-pressure barriers
#pragma unroll
        for (int c = 0; c < NCHUNK; c++) BAR_ARRIVE(4 + c, CNT_FWD);

        int par = 0;
        for (int t = 0; t < T_STEPS; t++) {
#pragma unroll
            for (int l = 0; l < 3; l++) {
                const __half* gw = g_wh + (size_t)l*NEL;
                int pin_g = (l == 0) ? 7 : (l == 1 ? 4 : 0);
                const __half* wpinL = (l == 0) ? wpin : wpin + rcount*CDIM;

                float a0 = 0.f, a1 = 0.f, a2 = 0.f;
                if (grp < pin_g) {
                    chunks_loop<true >(wpinL + l0*CDIM, wpinL + l1*CDIM, wpinL + l2*CDIM,
                                       sv, ks, lane, a0, a1, a2);
                } else {
                    chunks_loop<false>(gw + (size_t)(rstart+l0)*CDIM,
                                       gw + (size_t)(rstart+l1)*CDIM,
                                       gw + (size_t)(rstart+l2)*CDIM,
                                       sv, ks, lane, a0, a1, a2);
                }
#pragma unroll
                for (int o = 16; o; o >>= 1) {
                    a0 += __shfl_xor_sync(0xffffffffu, a0, o);
                    a1 += __shfl_xor_sync(0xffffffffu, a1, o);
                    a2 += __shfl_xor_sync(0xffffffffu, a2, o);
                }

                // post partials: spre[par][row][ks]
                float* sp = spre + (par*32)*4;
                if (lane == 0) {
                    if (r0   < rcount) sp[(r0  )*4 + ks] = a0;
                    if (r0+1 < rcount) sp[(r0+1)*4 + ks] = a1;
                    if (r0+2 < rcount) sp[(r0+2)*4 + ks] = a2;
                    if (ks != 0) {
                        __threadfence_block();
                        atomicAdd(&sdone[par*8 + grp], 1u);
                    }
                }

                if (ks == 0) {
                    // group leader: wait for 3 partners, combine, publish
                    if (lane == 0) {
                        volatile unsigned* p = &sdone[par*8 + grp];
                        while (*p != 3u) { }
                        *p = 0u;
                    }
                    __syncwarp();
                    if (lane < 3 && (r0 + lane) < rcount) {
                        int j = rstart + r0 + lane;
                        float4 q = *(float4*)(sp + (r0 + lane)*4);
                        float s = (q.x + q.y) + (q.z + q.w);
                        if (l == 0) {
                            __stcg(&g_h1[t&1][j], tanhf(s + pb1));
                        } else if (l == 1) {
                            __stcg(&g_h2[t&1][j], tanhf(s + pb2));
                        } else {
                            float o = s + pb3;
                            if (j < VOCAB) {
                                out[(size_t)t*VOCAB + j] = o;
                            } else {
                                __stcg(&g_state[t&1][j - VOCAB], o);
                                if (t == T_STEPS-1)
                                    out[(size_t)T_STEPS*VOCAB + (j - VOCAB)] = o;
                            }
                        }
                    }
                    __syncwarp();
                    if (lane == 0) {
                        __threadfence();                       // release rows
                        unsigned d = atomicAdd(&bdone[par], 1u) + 1u;
                        if (d == 7u) {
                            *((volatile unsigned*)&bdone[par]) = 0u;
                            bool skip0 = (l == 2);             // layer-3 chunk0 never polled
                            if (!(skip0 && klo == 0)) atomicAdd(&g_cnt[l][klo], 1u);
                            if (khi != klo) atomicAdd(&g_cnt[l][khi], 1u);
                        }
                    }
                }
                par ^= 1;
            }
        }
    }
}

extern "C" void kernel_launch(void* const* d_in, const int* in_sizes, int n_in,
                              void* d_out, int out_size) {
    const float* x  = (const float*)d_in[0];
    const float* st = (const float*)d_in[1];
    const float* W1 = (const float*)d_in[2];
    const float* B1 = (const float*)d_in[3];
    const float* W2 = (const float*)d_in[4];
    const float* B2 = (const float*)d_in[5];
    const float* W3 = (const float*)d_in[6];
    const float* B3 = (const float*)d_in[7];
    (void)in_sizes; (void)n_in; (void)out_size;

    cudaFuncSetAttribute(rnn_kernel, cudaFuncAttributeMaxDynamicSharedMemorySize, SMEM_TOTAL);

    conv_kernel<<<2048, 256>>>(W1, W2, W3);
    rnn_kernel<<<NBLK, NTHR, SMEM_TOTAL>>>(x, st, B1, B2, B3, (float*)d_out);
}

// round 9
// speedup vs baseline: 2.1098x; 1.7020x over previous
#include <cuda_runtime.h>
#include <cuda_fp16.h>
#include <math.h>

#define T_STEPS 4096
#define VOCAB   1024
#define STATE   2048
#define CDIM    3072
#define NEL     (CDIM*CDIM)
#define NBLK    148
#define NTHR    1024
#define NCOMPW  28
#define NCHUNK  3
#define CHUNK   1024
#define PIN_W2  12
#define PIN_BYTES ((21+PIN_W2)*CDIM*2)
#define SV_OFF    PIN_BYTES
#define SPRE_OFF  (SV_OFF + CDIM*4)
#define SMEM_TOTAL (SPRE_OFF + 4*32*4)

#define CNT_FWD (NCOMPW*32 + 32)
#define CNT_CMP (NCOMPW*32)
#define BAR_SYNC(id,cnt)   asm volatile("bar.sync %0, %1;"   :: "r"(id), "r"(cnt) : "memory")
#define BAR_ARRIVE(id,cnt) asm volatile("bar.arrive %0, %1;" :: "r"(id), "r"(cnt) : "memory")

__device__ __half   g_wf[(size_t)NEL];
__device__ __half   g_w2h[(size_t)NEL];
__device__ float    g_A[(size_t)T_STEPS*CDIM];
__device__ float    g_hist[(size_t)T_STEPS*CDIM];
__device__ float    g_cvec[CDIM];
__device__ float    g_h1[2][CDIM];
__device__ float    g_h2[2][CDIM];
__device__ unsigned g_cnt[2][NCHUNK];
__device__ unsigned g_scount, g_sflag;

__device__ __forceinline__ void start_barrier() {
    __syncthreads();
    if (threadIdx.x == 0) {
        unsigned F0;
        asm volatile("ld.volatile.global.u32 %0,[%1];" : "=r"(F0) : "l"(&g_sflag) : "memory");
        unsigned a = atomicAdd(&g_scount, 1u) + 1u;
        if (a == (unsigned)gridDim.x) {
            for (int l = 0; l < 2; l++)
                for (int k = 0; k < NCHUNK; k++) g_cnt[l][k] = 0u;
            atomicExch(&g_scount, 0u);
            __threadfence();
            atomicAdd(&g_sflag, 1u);
        } else {
            unsigned f;
            do {
                asm volatile("ld.volatile.global.u32 %0,[%1];" : "=r"(f) : "l"(&g_sflag) : "memory");
            } while (f == F0);
            __threadfence();
        }
    }
    __syncthreads();
}

__global__ void conv_kernel(const float* __restrict__ W2) {
    size_t i = (size_t)blockIdx.x * blockDim.x + threadIdx.x;
    size_t stride = (size_t)gridDim.x * blockDim.x;
    if (i < CDIM) g_h2[1][i] = 0.f;
    const float2* w2 = (const float2*)W2;
    __half2* o2 = (__half2*)g_w2h;
    for (; i < NEL/2; i += stride) {
        float2 v = w2[i]; o2[i] = __floats2half2_rn(v.x, v.y);
    }
}

__global__ void cvec_kernel(const float* __restrict__ W1, const float* __restrict__ B1,
                            const float* __restrict__ B3) {
    int row = blockIdx.x * 8 + (threadIdx.x >> 5);
    int lane = threadIdx.x & 31;
    if (row >= CDIM) return;
    const float* wr = W1 + (size_t)row*CDIM + VOCAB;
    float s = 0.f;
    for (int m = lane; m < STATE; m += 32) s += wr[m] * __ldg(&B3[VOCAB+m]);
#pragma unroll
    for (int o = 16; o; o >>= 1) s += __shfl_xor_sync(0xffffffffu, s, o);
    if (lane == 0) g_cvec[row] = s + B1[row];
}

__global__ void a0fix_kernel(const float* __restrict__ W1, const float* __restrict__ state0,
                             const float* __restrict__ B3) {
    int row = blockIdx.x * 8 + (threadIdx.x >> 5);
    int lane = threadIdx.x & 31;
    if (row >= CDIM) return;
    const float* wr = W1 + (size_t)row*CDIM + VOCAB;
    float s = 0.f;
    for (int m = lane; m < STATE; m += 32)
        s += wr[m] * (__ldg(&state0[m]) - __ldg(&B3[VOCAB+m]));
#pragma unroll
    for (int o = 16; o; o >>= 1) s += __shfl_xor_sync(0xffffffffu, s, o);
    if (lane == 0) g_A[row] += s;
}

__global__ void sfinal_kernel(const float* __restrict__ W3, const float* __restrict__ B3,
                              float* __restrict__ out) {
    int row = blockIdx.x * 8 + (threadIdx.x >> 5);
    int lane = threadIdx.x & 31;
    if (row >= STATE) return;
    const float* wr = W3 + (size_t)(VOCAB+row)*CDIM;
    const float* h = g_hist + (size_t)(T_STEPS-1)*CDIM;
    float s = 0.f;
    for (int m = lane; m < CDIM; m += 32) s += wr[m] * h[m];
#pragma unroll
    for (int o = 16; o; o >>= 1) s += __shfl_xor_sync(0xffffffffu, s, o);
    if (lane == 0) out[(size_t)T_STEPS*VOCAB + row] = s + __ldg(&B3[VOCAB+row]);
}

#define GBM 128
#define GBN 64
#define GBK 16

// MODE 0: g_A (fp32) = A@B^T + g_cvec      (A=x, B=W1, K=1024)
// MODE 1: out (fp32) = g_hist@B^T + bias   (B=W3, K=3072)
// MODE 2: g_wf (fp16) = A@B (NN)           (A=W1+1024, B=W3+1024*CDIM, K=2048)
template<int MODE>
__global__ __launch_bounds__(256)
void gemm_kernel(const float* __restrict__ A, const float* __restrict__ B,
                 const float* __restrict__ bias, float* __restrict__ Cout,
                 int K, int lda, int ldb, int ldc) {
    __shared__ float As[GBK][GBM], Bs[GBK][GBN];
    const int bm = blockIdx.y * GBM, bn = blockIdx.x * GBN;
    const int tid = threadIdx.x;
    const int tx = tid & 15, ty = tid >> 4;
    const int ar = tid >> 2, ac = (tid & 3) * 4;
    const int brk = tid >> 4, bc = (tid & 15) * 4;
    const float* Ap = (MODE == 1) ? g_hist : A;
    float acc[8][4];
#pragma unroll
    for (int i = 0; i < 8; i++)
#pragma unroll
        for (int j = 0; j < 4; j++) acc[i][j] = 0.f;

    for (int k0 = 0; k0 < K; k0 += GBK) {
        float4 a0 = *(const float4*)(Ap + (size_t)(bm+ar)*lda + k0 + ac);
        float4 a1 = *(const float4*)(Ap + (size_t)(bm+ar+64)*lda + k0 + ac);
        As[ac+0][ar] = a0.x; As[ac+1][ar] = a0.y; As[ac+2][ar] = a0.z; As[ac+3][ar] = a0.w;
        As[ac+0][ar+64] = a1.x; As[ac+1][ar+64] = a1.y; As[ac+2][ar+64] = a1.z; As[ac+3][ar+64] = a1.w;
        if (MODE == 2) {
            float4 b0 = *(const float4*)(B + (size_t)(k0+brk)*ldb + bn + bc);
            *(float4*)&Bs[brk][bc] = b0;
        } else {
            float4 b0 = *(const float4*)(B + (size_t)(bn+ar)*ldb + k0 + ac);
            Bs[ac+0][ar] = b0.x; Bs[ac+1][ar] = b0.y; Bs[ac+2][ar] = b0.z; Bs[ac+3][ar] = b0.w;
        }
        __syncthreads();
#pragma unroll
        for (int kk = 0; kk < GBK; kk++) {
            float4 av0 = *(const float4*)&As[kk][ty*8];
            float4 av1 = *(const float4*)&As[kk][ty*8+4];
            float4 bv  = *(const float4*)&Bs[kk][tx*4];
            float a[8] = {av0.x,av0.y,av0.z,av0.w,av1.x,av1.y,av1.z,av1.w};
            float bb[4] = {bv.x,bv.y,bv.z,bv.w};
#pragma unroll
            for (int i = 0; i < 8; i++)
#pragma unroll
                for (int j = 0; j < 4; j++) acc[i][j] = fmaf(a[i], bb[j], acc[i][j]);
        }
        __syncthreads();
    }
#pragma unroll
    for (int i = 0; i < 8; i++) {
        int m = bm + ty*8 + i;
#pragma unroll
        for (int j = 0; j < 4; j++) {
            int n = bn + tx*4 + j;
            if (MODE == 2) {
                g_wf[(size_t)m*ldc + n] = __float2half_rn(acc[i][j]);
            } else if (MODE == 0) {
                g_A[(size_t)m*ldc + n] = acc[i][j] + __ldg(&g_cvec[n]);
            } else {
                Cout[(size_t)m*ldc + n] = acc[i][j] + __ldg(&bias[n]);
            }
        }
    }
}

template<bool PIN>
__device__ __forceinline__ void chunks_loop(
    const __half* w0, const __half* w1, const __half* w2,
    const float* __restrict__ sv, int ks, int lane,
    float& a0, float& a1, float& a2)
{
#pragma unroll
    for (int c = 0; c < NCHUNK; c++) {
        BAR_SYNC(1 + c, CNT_FWD);
        int kb = c*CHUNK + ks*256;
#pragma unroll
        for (int i = 0; i < 2; i++) {
            int k = kb + (i*32 + lane)*4;
            float4 v = *(const float4*)(sv + k);
#define ROW(AC, WP) do {                                                   \
            uint2 wa = PIN ? *(const uint2*)((WP) + k)                     \
                           : __ldg((const uint2*)((WP) + k));              \
            float2 fa = __half22float2(*(const __half2*)&wa.x);            \
            float2 fb = __half22float2(*(const __half2*)&wa.y);            \
            AC = fmaf(fa.x, v.x, AC); AC = fmaf(fa.y, v.y, AC);            \
            AC = fmaf(fb.x, v.z, AC); AC = fmaf(fb.y, v.w, AC); } while (0)
            ROW(a0, w0); ROW(a1, w1); ROW(a2, w2);
#undef ROW
        }
        BAR_ARRIVE(4 + c, CNT_FWD);
    }
}

__global__ void __launch_bounds__(NTHR, 1)
rnn_kernel(const float* __restrict__ B2) {
    extern __shared__ char smem[];
    __half* wpin = (__half*)smem;
    float*  sv   = (float*)(smem + SV_OFF);
    float*  spre = (float*)(smem + SPRE_OFF);

    const int tid  = threadIdx.x;
    const int lane = tid & 31;
    const int warp = tid >> 5;
    const int b    = blockIdx.x;

    const int rcount = 20 + (b < 112 ? 1 : 0);
    const int rstart = b*20 + (b < 112 ? b : 112);
    const int klo = rstart >> 10;
    const int khi = (rstart + rcount - 1) >> 10;

    start_barrier();

    {
        const int npin = rcount + PIN_W2;
        int nvec = npin * (CDIM/8);
        for (int idx = tid; idx < nvec; idx += NTHR) {
            int p = idx / (CDIM/8);
            int c = idx % (CDIM/8);
            const __half* base = (p < rcount) ? g_wf : g_w2h;
            int local = (p < rcount) ? p : p - rcount;
            const uint4* src = (const uint4*)(base + (size_t)(rstart+local)*CDIM);
            ((uint4*)(wpin + p*CDIM))[c] = src[c];
        }
    }
    __syncthreads();

    if (warp == 31) return;

    int Tk[NCHUNK];
#pragma unroll
    for (int k = 0; k < NCHUNK; k++) {
        int cnt = 0;
        for (int bb = 0; bb < NBLK; bb++) {
            int rs = 20*bb + (bb < 112 ? bb : 112);
            int rc = 20 + (bb < 112 ? 1 : 0);
            if (rs < (k+1)*CHUNK && rs + rc > k*CHUNK) cnt++;
        }
        Tk[k] = cnt;
    }

    if (warp >= NCOMPW) {
        const int c = warp - NCOMPW;
        const unsigned Tc = (unsigned)Tk[c];
        for (int t = 0; t < T_STEPS; t++) {
#pragma unroll
            for (int l = 0; l < 2; l++) {
                BAR_SYNC(4 + c, CNT_FWD);
                const float* src;
                const unsigned* cp;
                unsigned tgt;
                if (l == 0) {
                    cp = &g_cnt[1][c]; tgt = (unsigned)t * Tc;
                    src = g_h2[(t-1)&1] + c*CHUNK;
                } else {
                    cp = &g_cnt[0][c]; tgt = (unsigned)(t+1) * Tc;
                    src = g_h1[t&1] + c*CHUNK;
                }
                if (tgt != 0 && lane == 0) {
                    unsigned v;
                    do {
                        asm volatile("ld.volatile.global.u32 %0,[%1];" : "=r"(v) : "l"(cp) : "memory");
                    } while (v < tgt);
                    __threadfence();
                }
                __syncwarp();
                const float4* s4 = (const float4*)src;
                float4* d4 = (float4*)(sv + c*CHUNK);
#pragma unroll
                for (int i = 0; i < CHUNK/128; i++)
                    d4[lane + 32*i] = __ldcg(&s4[lane + 32*i]);
                __threadfence_block();
                BAR_ARRIVE(1 + c, CNT_FWD);
            }
        }
    } else {
        const int grp = warp >> 2;
        const int ks  = warp & 3;
        const int r0  = grp*3;
        const int l0 = min(r0,   rcount-1);
        const int l1 = min(r0+1, rcount-1);
        const int l2 = min(r0+2, rcount-1);

        float myB2 = 0.f;
        if (tid < rcount) myB2 = __ldg(&B2[rstart+tid]);

#pragma unroll
        for (int c = 0; c < NCHUNK; c++) BAR_ARRIVE(4 + c, CNT_FWD);

        for (int t = 0; t < T_STEPS; t++) {
#pragma unroll
            for (int l = 0; l < 2; l++) {
                float myA = 0.f;
                if (l == 0 && tid < rcount)
                    myA = __ldg(&g_A[(size_t)t*CDIM + rstart + tid]);

                float a0 = 0.f, a1 = 0.f, a2 = 0.f;
                if (l == 0) {
                    chunks_loop<true >(wpin + l0*CDIM, wpin + l1*CDIM, wpin + l2*CDIM,
                                       sv, ks, lane, a0, a1, a2);
                } else if (grp < 4) {
                    const __half* wp2 = wpin + rcount*CDIM;
                    chunks_loop<true >(wp2 + l0*CDIM, wp2 + l1*CDIM, wp2 + l2*CDIM,
                                       sv, ks, lane, a0, a1, a2);
                } else {
                    chunks_loop<false>(g_w2h + (size_t)(rstart+l0)*CDIM,
                                       g_w2h + (size_t)(rstart+l1)*CDIM,
                                       g_w2h + (size_t)(rstart+l2)*CDIM,
                                       sv, ks, lane, a0, a1, a2);
                }
#pragma unroll
                for (int o = 16; o; o >>= 1) {
                    a0 += __shfl_xor_sync(0xffffffffu, a0, o);
                    a1 += __shfl_xor_sync(0xffffffffu, a1, o);
                    a2 += __shfl_xor_sync(0xffffffffu, a2, o);
                }
                if (lane == 0) {
                    if (r0   < rcount) spre[ks*32 + r0  ] = a0;
                    if (r0+1 < rcount) spre[ks*32 + r0+1] = a1;
                    if (r0+2 < rcount) spre[ks*32 + r0+2] = a2;
                }
                BAR_SYNC(7, CNT_CMP);

                if (tid < rcount) {
                    int j = rstart + tid;
                    float s = spre[tid] + spre[32+tid] + spre[64+tid] + spre[96+tid];
                    if (l == 0) {
                        __stcg(&g_h1[t&1][j], tanhf(s + myA));
                    } else {
                        float h = tanhf(s + myB2);
                        __stcg(&g_h2[t&1][j], h);
                        g_hist[(size_t)t*CDIM + j] = h;
                    }
                }
                if (warp == 0) {
                    __syncwarp();
                    if (lane == 0) {
                        __threadfence();
                        atomicAdd(&g_cnt[l][klo], 1u);
                        if (khi != klo) atomicAdd(&g_cnt[l][khi], 1u);
                    }
                }
                BAR_SYNC(8, CNT_CMP);
            }
        }
    }
}

extern "C" void kernel_launch(void* const* d_in, const int* in_sizes, int n_in,
                              void* d_out, int out_size) {
    const float* x  = (const float*)d_in[0];
    const float* st = (const float*)d_in[1];
    const float* W1 = (const float*)d_in[2];
    const float* B1 = (const float*)d_in[3];
    const float* W2 = (const float*)d_in[4];
    const float* B2 = (const float*)d_in[5];
    const float* W3 = (const float*)d_in[6];
    const float* B3 = (const float*)d_in[7];
    (void)in_sizes; (void)n_in; (void)out_size;
    float* out = (float*)d_out;

    cudaFuncSetAttribute(rnn_kernel, cudaFuncAttributeMaxDynamicSharedMemorySize, SMEM_TOTAL);

    conv_kernel<<<2048, 256>>>(W2);
    cvec_kernel<<<384, 256>>>(W1, B1, B3);

    // Wf (fp16) = W1[:,1024:] @ W3[1024:,:]   (MODE 2, NN)
    {
        dim3 g(CDIM/GBN, CDIM/GBM);
        gemm_kernel<2><<<g, 256>>>(W1 + VOCAB, W3 + (size_t)VOCAB*CDIM,
                                   (const float*)0, (float*)0, STATE, CDIM, CDIM, CDIM);
    }
    // A = x @ W1x^T + C   (MODE 0, NT)
    {
        dim3 g(CDIM/GBN, T_STEPS/GBM);
        gemm_kernel<0><<<g, 256>>>(x, W1, (const float*)0, (float*)0, VOCAB, VOCAB, CDIM, CDIM);
    }
    a0fix_kernel<<<384, 256>>>(W1, st, B3);

    rnn_kernel<<<NBLK, NTHR, SMEM_TOTAL>>>(B2);

    // logits: out = hist @ W3v^T + B3v   (MODE 1, NT)
    {
        dim3 g(VOCAB/GBN, T_STEPS/GBM);
        gemm_kernel<1><<<g, 256>>>((const float*)0, W3, B3, out, CDIM, CDIM, CDIM, VOCAB);
    }
    sfinal_kernel<<<256, 256>>>(W3, B3, out);
}

// round 12
// speedup vs baseline: 2.2710x; 1.0764x over previous
#include <cuda_runtime.h>
#include <cuda_fp16.h>
#include <math.h>

#define T_STEPS 4096
#define VOCAB   1024
#define STATE   2048
#define CDIM    3072
#define NEL     (CDIM*CDIM)
#define NBLK    148
#define NTHR    1024
#define NCOMPW  28
#define NCHUNK  3
#define CHUNK   1024
#define PIN_W2  12
#define PIN_BYTES ((21+PIN_W2)*CDIM*2)
#define SV_OFF    PIN_BYTES
#define SPRE_OFF  (SV_OFF + CDIM*4)
#define SMEM_TOTAL (SPRE_OFF + 2*128*4)      // spre[2][128]

#define CNT_FWD (NCOMPW*32 + 32)   // 928: compute + 1 stager
#define CNT_PUB (NCOMPW*32 + 32)   // 928: compute arrive + publisher sync
#define BAR_SYNC(id,cnt)   asm volatile("bar.sync %0, %1;"   :: "r"(id), "r"(cnt) : "memory")
#define BAR_ARRIVE(id,cnt) asm volatile("bar.arrive %0, %1;" :: "r"(id), "r"(cnt) : "memory")

__device__ __half   g_wf[(size_t)NEL];
__device__ __half   g_w2h[(size_t)NEL];
__device__ float    g_A[(size_t)T_STEPS*CDIM];
__device__ float    g_hist[(size_t)T_STEPS*CDIM];
__device__ float    g_cvec[CDIM];
__device__ float    g_h1[2][CDIM];
__device__ float    g_h2[2][CDIM];
__device__ unsigned g_cnt[2][NCHUNK];
__device__ unsigned g_scount, g_sflag;

__device__ __forceinline__ void start_barrier() {
    __syncthreads();
    if (threadIdx.x == 0) {
        unsigned F0;
        asm volatile("ld.volatile.global.u32 %0,[%1];" : "=r"(F0) : "l"(&g_sflag) : "memory");
        unsigned a = atomicAdd(&g_scount, 1u) + 1u;
        if (a == (unsigned)gridDim.x) {
            for (int l = 0; l < 2; l++)
                for (int k = 0; k < NCHUNK; k++) g_cnt[l][k] = 0u;
            atomicExch(&g_scount, 0u);
            __threadfence();
            atomicAdd(&g_sflag, 1u);
        } else {
            unsigned f;
            do {
                asm volatile("ld.volatile.global.u32 %0,[%1];" : "=r"(f) : "l"(&g_sflag) : "memory");
            } while (f == F0);
            __threadfence();
        }
    }
    __syncthreads();
}

__global__ void conv_kernel(const float* __restrict__ W2) {
    size_t i = (size_t)blockIdx.x * blockDim.x + threadIdx.x;
    size_t stride = (size_t)gridDim.x * blockDim.x;
    if (i < CDIM) g_h2[1][i] = 0.f;
    const float2* w2 = (const float2*)W2;
    __half2* o2 = (__half2*)g_w2h;
    for (; i < NEL/2; i += stride) {
        float2 v = w2[i]; o2[i] = __floats2half2_rn(v.x, v.y);
    }
}

__global__ void cvec_kernel(const float* __restrict__ W1, const float* __restrict__ B1,
                            const float* __restrict__ B3) {
    int row = blockIdx.x * 8 + (threadIdx.x >> 5);
    int lane = threadIdx.x & 31;
    if (row >= CDIM) return;
    const float* wr = W1 + (size_t)row*CDIM + VOCAB;
    float s = 0.f;
    for (int m = lane; m < STATE; m += 32) s += wr[m] * __ldg(&B3[VOCAB+m]);
#pragma unroll
    for (int o = 16; o; o >>= 1) s += __shfl_xor_sync(0xffffffffu, s, o);
    if (lane == 0) g_cvec[row] = s + B1[row];
}

__global__ void a0fix_kernel(const float* __restrict__ W1, const float* __restrict__ state0,
                             const float* __restrict__ B3) {
    int row = blockIdx.x * 8 + (threadIdx.x >> 5);
    int lane = threadIdx.x & 31;
    if (row >= CDIM) return;
    const float* wr = W1 + (size_t)row*CDIM + VOCAB;
    float s = 0.f;
    for (int m = lane; m < STATE; m += 32)
        s += wr[m] * (__ldg(&state0[m]) - __ldg(&B3[VOCAB+m]));
#pragma unroll
    for (int o = 16; o; o >>= 1) s += __shfl_xor_sync(0xffffffffu, s, o);
    if (lane == 0) g_A[row] += s;
}

__global__ void sfinal_kernel(const float* __restrict__ W3, const float* __restrict__ B3,
                              float* __restrict__ out) {
    int row = blockIdx.x * 8 + (threadIdx.x >> 5);
    int lane = threadIdx.x & 31;
    if (row >= STATE) return;
    const float* wr = W3 + (size_t)(VOCAB+row)*CDIM;
    const float* h = g_hist + (size_t)(T_STEPS-1)*CDIM;
    float s = 0.f;
    for (int m = lane; m < CDIM; m += 32) s += wr[m] * h[m];
#pragma unroll
    for (int o = 16; o; o >>= 1) s += __shfl_xor_sync(0xffffffffu, s, o);
    if (lane == 0) out[(size_t)T_STEPS*VOCAB + row] = s + __ldg(&B3[VOCAB+row]);
}

#define GBM 128
#define GBN 64
#define GBK 16

template<int MODE>
__global__ __launch_bounds__(256)
void gemm_kernel(const float* __restrict__ A, const float* __restrict__ B,
                 const float* __restrict__ bias, float* __restrict__ Cout,
                 int K, int lda, int ldb, int ldc) {
    __shared__ float As[GBK][GBM], Bs[GBK][GBN];
    const int bm = blockIdx.y * GBM, bn = blockIdx.x * GBN;
    const int tid = threadIdx.x;
    const int tx = tid & 15, ty = tid >> 4;
    const int ar = tid >> 2, ac = (tid & 3) * 4;
    const int brk = tid >> 4, bc = (tid & 15) * 4;
    const float* Ap = (MODE == 1) ? g_hist : A;
    float acc[8][4];
#pragma unroll
    for (int i = 0; i < 8; i++)
#pragma unroll
        for (int j = 0; j < 4; j++) acc[i][j] = 0.f;

    for (int k0 = 0; k0 < K; k0 += GBK) {
        float4 a0 = *(const float4*)(Ap + (size_t)(bm+ar)*lda + k0 + ac);
        float4 a1 = *(const float4*)(Ap + (size_t)(bm+ar+64)*lda + k0 + ac);
        As[ac+0][ar] = a0.x; As[ac+1][ar] = a0.y; As[ac+2][ar] = a0.z; As[ac+3][ar] = a0.w;
        As[ac+0][ar+64] = a1.x; As[ac+1][ar+64] = a1.y; As[ac+2][ar+64] = a1.z; As[ac+3][ar+64] = a1.w;
        if (MODE == 2) {
            float4 b0 = *(const float4*)(B + (size_t)(k0+brk)*ldb + bn + bc);
            *(float4*)&Bs[brk][bc] = b0;
        } else {
            float4 b0 = *(const float4*)(B + (size_t)(bn+ar)*ldb + k0 + ac);
            Bs[ac+0][ar] = b0.x; Bs[ac+1][ar] = b0.y; Bs[ac+2][ar] = b0.z; Bs[ac+3][ar] = b0.w;
        }
        __syncthreads();
#pragma unroll
        for (int kk = 0; kk < GBK; kk++) {
            float4 av0 = *(const float4*)&As[kk][ty*8];
            float4 av1 = *(const float4*)&As[kk][ty*8+4];
            float4 bv  = *(const float4*)&Bs[kk][tx*4];
            float a[8] = {av0.x,av0.y,av0.z,av0.w,av1.x,av1.y,av1.z,av1.w};
            float bb[4] = {bv.x,bv.y,bv.z,bv.w};
#pragma unroll
            for (int i = 0; i < 8; i++)
#pragma unroll
                for (int j = 0; j < 4; j++) acc[i][j] = fmaf(a[i], bb[j], acc[i][j]);
        }
        __syncthreads();
    }
#pragma unroll
    for (int i = 0; i < 8; i++) {
        int m = bm + ty*8 + i;
#pragma unroll
        for (int j = 0; j < 4; j++) {
            int n = bn + tx*4 + j;
            if (MODE == 2) {
                g_wf[(size_t)m*ldc + n] = __float2half_rn(acc[i][j]);
            } else if (MODE == 0) {
                g_A[(size_t)m*ldc + n] = acc[i][j] + __ldg(&g_cvec[n]);
            } else {
                Cout[(size_t)m*ldc + n] = acc[i][j] + __ldg(&bias[n]);
            }
        }
    }
}

template<bool PIN>
__device__ __forceinline__ void chunks_loop(
    const __half* w0, const __half* w1, const __half* w2,
    const float* __restrict__ sv, int ks, int lane,
    float& a0, float& a1, float& a2)
{
#pragma unroll
    for (int c = 0; c < NCHUNK; c++) {
        BAR_SYNC(1 + c, CNT_FWD);
        int kb = c*CHUNK + ks*256;
#pragma unroll
        for (int i = 0; i < 2; i++) {
            int k = kb + (i*32 + lane)*4;
            float4 v = *(const float4*)(sv + k);
#define ROW(AC, WP) do {                                                   \
            uint2 wa = PIN ? *(const uint2*)((WP) + k)                     \
                           : __ldg((const uint2*)((WP) + k));              \
            float2 fa = __half22float2(*(const __half2*)&wa.x);            \
            float2 fb = __half22float2(*(const __half2*)&wa.y);            \
            AC = fmaf(fa.x, v.x, AC); AC = fmaf(fa.y, v.y, AC);            \
            AC = fmaf(fb.x, v.z, AC); AC = fmaf(fb.y, v.w, AC); } while (0)
            ROW(a0, w0); ROW(a1, w1); ROW(a2, w2);
#undef ROW
        }
        BAR_ARRIVE(4 + c, CNT_FWD);
    }
}

__global__ void __launch_bounds__(NTHR, 1)
rnn_kernel(const float* __restrict__ B2) {
    extern __shared__ char smem[];
    __half* wpin = (__half*)smem;
    float*  sv   = (float*)(smem + SV_OFF);
    float*  spre = (float*)(smem + SPRE_OFF);   // [2][128]

    const int tid  = threadIdx.x;
    const int lane = tid & 31;
    const int warp = tid >> 5;
    const int b    = blockIdx.x;

    const int rcount = 20 + (b < 112 ? 1 : 0);
    const int rstart = b*20 + (b < 112 ? b : 112);
    const int klo = rstart >> 10;
    const int khi = (rstart + rcount - 1) >> 10;

    start_barrier();

    {
        const int npin = rcount + PIN_W2;
        int nvec = npin * (CDIM/8);
        for (int idx = tid; idx < nvec; idx += NTHR) {
            int p = idx / (CDIM/8);
            int c = idx % (CDIM/8);
            const __half* base = (p < rcount) ? g_wf : g_w2h;
            int local = (p < rcount) ? p : p - rcount;
            const uint4* src = (const uint4*)(base + (size_t)(rstart+local)*CDIM);
            ((uint4*)(wpin + p*CDIM))[c] = src[c];
        }
    }
    __syncthreads();

    int Tk[NCHUNK];
#pragma unroll
    for (int k = 0; k < NCHUNK; k++) {
        int cnt = 0;
        for (int bb = 0; bb < NBLK; bb++) {
            int rs = 20*bb + (bb < 112 ? bb : 112);
            int rc = 20 + (bb < 112 ? 1 : 0);
            if (rs < (k+1)*CHUNK && rs + rc > k*CHUNK) cnt++;
        }
        Tk[k] = cnt;
    }

    if (warp >= NCOMPW && warp < NCOMPW + 3) {
        // ================= STAGER WARP (warps 28-30, one chunk each) =================
        const int c = warp - NCOMPW;
        const unsigned Tc = (unsigned)Tk[c];
        for (int t = 0; t < T_STEPS; t++) {
#pragma unroll
            for (int l = 0; l < 2; l++) {
                BAR_SYNC(4 + c, CNT_FWD);       // back-pressure (primed)
                const float* src;
                const unsigned* cp;
                unsigned tgt;
                if (l == 0) {
                    cp = &g_cnt[1][c]; tgt = (unsigned)t * Tc;
                    src = g_h2[(t-1)&1] + c*CHUNK;
                } else {
                    cp = &g_cnt[0][c]; tgt = (unsigned)(t+1) * Tc;
                    src = g_h1[t&1] + c*CHUNK;
                }
                if (tgt != 0 && lane == 0) {
                    unsigned v;
                    do {
                        asm volatile("ld.acquire.gpu.global.u32 %0,[%1];" : "=r"(v) : "l"(cp) : "memory");
                    } while (v < tgt);
                }
                __syncwarp();
                const float4* s4 = (const float4*)src;
                float4* d4 = (float4*)(sv + c*CHUNK);
#pragma unroll
                for (int i = 0; i < CHUNK/128; i++)
                    d4[lane + 32*i] = __ldcg(&s4[lane + 32*i]);
                __threadfence_block();
                BAR_ARRIVE(1 + c, CNT_FWD);
            }
        }
    } else if (warp == 31) {
        // ================= PUBLISHER WARP =================
        float myB2 = 0.f;
        if (lane < rcount) myB2 = __ldg(&B2[rstart+lane]);
        int par = 0;
        for (int t = 0; t < T_STEPS; t++) {
#pragma unroll
            for (int l = 0; l < 2; l++) {
                float myA = 0.f;
                if (l == 0 && lane < rcount)
                    myA = __ldg(&g_A[(size_t)t*CDIM + rstart + lane]);
                BAR_SYNC(7 + par, CNT_PUB);     // all compute partials posted
                if (lane < rcount) {
                    int j = rstart + lane;
                    const float* q = spre + par*128;
                    float s = q[lane] + q[32+lane] + q[64+lane] + q[96+lane];
                    if (l == 0) {
                        __stcg(&g_h1[t&1][j], tanhf(s + myA));
                    } else {
                        float h = tanhf(s + myB2);
                        __stcg(&g_h2[t&1][j], h);
                        g_hist[(size_t)t*CDIM + j] = h;
                    }
                }
                __syncwarp();
                if (lane == 0) {
                    asm volatile("red.release.gpu.global.add.u32 [%0], %1;"
                                 :: "l"(&g_cnt[l][klo]), "r"(1u) : "memory");
                    if (khi != klo)
                        asm volatile("red.release.gpu.global.add.u32 [%0], %1;"
                                     :: "l"(&g_cnt[l][khi]), "r"(1u) : "memory");
                }
                par ^= 1;
            }
        }
    } else {
        // ================= COMPUTE WARP (0-27) =================
        const int grp = warp >> 2;
        const int ks  = warp & 3;
        const int r0  = grp*3;
        const int l0 = min(r0,   rcount-1);
        const int l1 = min(r0+1, rcount-1);
        const int l2 = min(r0+2, rcount-1);

#pragma unroll
        for (int c = 0; c < NCHUNK; c++) BAR_ARRIVE(4 + c, CNT_FWD);   // prime

        int par = 0;
        for (int t = 0; t < T_STEPS; t++) {
#pragma unroll
            for (int l = 0; l < 2; l++) {
                float a0 = 0.f, a1 = 0.f, a2 = 0.f;
                if (l == 0) {
                    chunks_loop<true >(wpin + l0*CDIM, wpin + l1*CDIM, wpin + l2*CDIM,
                                       sv, ks, lane, a0, a1, a2);
                } else if (grp < 4) {
                    const __half* wp2 = wpin + rcount*CDIM;
                    chunks_loop<true >(wp2 + l0*CDIM, wp2 + l1*CDIM, wp2 + l2*CDIM,
                                       sv, ks, lane, a0, a1, a2);
                } else {
                    chunks_loop<false>(g_w2h + (size_t)(rstart+l0)*CDIM,
                                       g_w2h + (size_t)(rstart+l1)*CDIM,
                                       g_w2h + (size_t)(rstart+l2)*CDIM,
                                       sv, ks, lane, a0, a1, a2);
                }
#pragma unroll
                for (int o = 16; o; o >>= 1) {
                    a0 += __shfl_xor_sync(0xffffffffu, a0, o);
                    a1 += __shfl_xor_sync(0xffffffffu, a1, o);
                    a2 += __shfl_xor_sync(0xffffffffu, a2, o);
                }
                float* sp = spre + par*128 + ks*32;
                if (lane == 0) {
                    if (r0   < rcount) sp[r0  ] = a0;
                    if (r0+1 < rcount) sp[r0+1] = a1;
                    if (r0+2 < rcount) sp[r0+2] = a2;
                }
                __threadfence_block();          // order STS before arrive
                BAR_ARRIVE(7 + par, CNT_PUB);   // non-blocking: flow to next phase
                par ^= 1;
            }
        }
    }
}

extern "C" void kernel_launch(void* const* d_in, const int* in_sizes, int n_in,
                              void* d_out, int out_size) {
    const float* x  = (const float*)d_in[0];
    const float* st = (const float*)d_in[1];
    const float* W1 = (const float*)d_in[2];
    const float* B1 = (const float*)d_in[3];
    const float* W2 = (const float*)d_in[4];
    const float* B2 = (const float*)d_in[5];
    const float* W3 = (const float*)d_in[6];
    const float* B3 = (const float*)d_in[7];
    (void)in_sizes; (void)n_in; (void)out_size;
    float* out = (float*)d_out;

    cudaFuncSetAttribute(rnn_kernel, cudaFuncAttributeMaxDynamicSharedMemorySize, SMEM_TOTAL);

    conv_kernel<<<2048, 256>>>(W2);
    cvec_kernel<<<384, 256>>>(W1, B1, B3);

    {   // Wf (fp16) = W1[:,1024:] @ W3[1024:,:]
        dim3 g(CDIM/GBN, CDIM/GBM);
        gemm_kernel<2><<<g, 256>>>(W1 + VOCAB, W3 + (size_t)VOCAB*CDIM,
                                   (const float*)0, (float*)0, STATE, CDIM, CDIM, CDIM);
    }
    {   // A = x @ W1x^T + C
        dim3 g(CDIM/GBN, T_STEPS/GBM);
        gemm_kernel<0><<<g, 256>>>(x, W1, (const float*)0, (float*)0, VOCAB, VOCAB, CDIM, CDIM);
    }
    a0fix_kernel<<<384, 256>>>(W1, st, B3);

    rnn_kernel<<<NBLK, NTHR, SMEM_TOTAL>>>(B2);

    {   // logits: out = hist @ W3v^T + B3v
        dim3 g(VOCAB/GBN, T_STEPS/GBM);
        gemm_kernel<1><<<g, 256>>>((const float*)0, W3, B3, out, CDIM, CDIM, CDIM, VOCAB);
    }
    sfinal_kernel<<<256, 256>>>(W3, B3, out);
}